// round 8
// baseline (speedup 1.0000x reference)
#include <cuda_runtime.h>
#include <cuda_bf16.h>
#include <cstdint>

typedef unsigned long long u64;

constexpr int Bc = 2;
constexpr int Lc = 4096;
constexpr int DK = 128;
constexpr int DV = 128;
constexpr int C  = 64;           // k3 chunk
constexpr int NC = Lc / C;       // 64 chunks/batch
constexpr int TC = Bc * NC;      // 128
constexpr int NS = 128;          // sub-chunks per batch (l-halves of 32)
constexpr int TS = Bc * NS;      // 256 sub-chunks total
constexpr float EPS = 1e-6f;

constexpr int PK = 130;          // k-contig stride (Q, K, Spre)
constexpr int PJ = 66;           // j-contig stride (A)
constexpr int PL = 66;           // l-contig stride (Vt)

// g_kv / g_kvpre: [sub][v][k] (k contiguous). g_ks: [sub][k].
__device__ float g_kv   [(size_t)TS * DK * DV];
__device__ float g_kvpre[(size_t)TS * DK * DV];
__device__ float g_ks   [(size_t)TS * DK];
__device__ float g_kspre[(size_t)TS * DK];

__device__ __forceinline__ float phi(float x) {
    return x > 0.f ? x + 1.f : __expf(x);
}
__device__ __forceinline__ void fma2(u64& d, u64 a, u64 b) {
    asm("fma.rn.f32x2 %0, %1, %2, %0;" : "+l"(d) : "l"(a), "l"(b));
}
__device__ __forceinline__ float2 up2(u64 v) {
    float2 f; asm("mov.b64 {%0, %1}, %2;" : "=f"(f.x), "=f"(f.y) : "l"(v)); return f;
}
__device__ __forceinline__ u64 dup2(float x) {
    u64 r; asm("mov.b64 %0, {%1, %1};" : "=l"(r) : "f"(x)); return r;
}
__device__ __forceinline__ u64 lds64(const float* p) {
    return *reinterpret_cast<const u64*>(p);
}

// ---------------------------------------------------------------------------
// Kernel 1: partial KV over an l-half, for a k-half.
// grid = 512: id = (bc, l-half, k-half). 256 thr, 24KB smem, 4 CTA/SM.
// Tile 8k x 4v per thread; a = natural k-pair lds64, b = dup(V scalar).
// ---------------------------------------------------------------------------
__global__ void __launch_bounds__(256, 4)
k_chunk_kv(const float* __restrict__ K, const float* __restrict__ V) {
    __shared__ float sKh[32 * 64];    // [l][k-half]  8 KB
    __shared__ float sVh[32 * 128];   // [l][v]      16 KB

    const int id = blockIdx.x;
    const int bc = id >> 2;
    const int lh = (id >> 1) & 1;
    const int kh = (id & 1) * 64;
    const int b  = bc / NC;
    const int c  = bc % NC;
    const int l0 = c * C + lh * 32;
    const int sub = bc * 2 + lh;          // = b*NS + (c*2+lh)
    const int tid = threadIdx.x;

    // stage phiK half: coalesced LDG.128 -> conflict-free STS.128
    for (int e = tid; e < 512; e += 256) {
        const int l = e >> 4, k4 = (e & 15) * 4;
        float4 x = *(const float4*)&K[((size_t)(b * Lc + l0 + l)) * DK + kh + k4];
        *(float4*)&sKh[l * 64 + k4] = make_float4(phi(x.x), phi(x.y), phi(x.z), phi(x.w));
    }
    // stage V half-chunk (full v): coalesced
    for (int e = tid; e < 1024; e += 256) {
        const int l = e >> 5, v4 = (e & 31) * 4;
        float4 x = *(const float4*)&V[((size_t)(b * Lc + l0 + l)) * DV + v4];
        *(float4*)&sVh[l * 128 + v4] = x;
    }
    __syncthreads();

    const int w = tid >> 5, tx = tid & 31;
    const int kloc = w * 8;               // warp-uniform k-group (8 k's)
    const int v0 = tx * 4;                // 4 consecutive v

    u64 acc[4][4];                        // [k-pair][v]
#pragma unroll
    for (int r = 0; r < 4; r++)
#pragma unroll
        for (int s = 0; s < 4; s++) acc[r][s] = 0ull;

#pragma unroll 4
    for (int l = 0; l < 32; l++) {
        const float* kr = &sKh[l * 64 + kloc];
        u64 a0 = lds64(kr), a1 = lds64(kr + 2), a2 = lds64(kr + 4), a3 = lds64(kr + 6);
        float4 bv = *(const float4*)&sVh[l * 128 + v0];
        u64 b0 = dup2(bv.x), b1 = dup2(bv.y), b2 = dup2(bv.z), b3 = dup2(bv.w);
        fma2(acc[0][0], a0, b0); fma2(acc[0][1], a0, b1);
        fma2(acc[0][2], a0, b2); fma2(acc[0][3], a0, b3);
        fma2(acc[1][0], a1, b0); fma2(acc[1][1], a1, b1);
        fma2(acc[1][2], a1, b2); fma2(acc[1][3], a1, b3);
        fma2(acc[2][0], a2, b0); fma2(acc[2][1], a2, b1);
        fma2(acc[2][2], a2, b2); fma2(acc[2][3], a2, b3);
        fma2(acc[3][0], a3, b0); fma2(acc[3][1], a3, b1);
        fma2(acc[3][2], a3, b2); fma2(acc[3][3], a3, b3);
    }

    // store g_kv[sub][v][k]: per v two float4 over k (aligned, k base mult of 8)
    float* kvout = g_kv + (size_t)sub * DK * DV;
#pragma unroll
    for (int s = 0; s < 4; s++) {
        const int v = v0 + s;
        float2 p0 = up2(acc[0][s]), p1 = up2(acc[1][s]);
        float2 p2 = up2(acc[2][s]), p3 = up2(acc[3][s]);
        *(float4*)&kvout[(size_t)v * DK + kh + kloc]     = make_float4(p0.x, p0.y, p1.x, p1.y);
        *(float4*)&kvout[(size_t)v * DK + kh + kloc + 4] = make_float4(p2.x, p2.y, p3.x, p3.y);
    }

    // per-sub-chunk phiK column sums for this k-half
    if (tid < 64) {
        float s = 0.f;
#pragma unroll 8
        for (int l = 0; l < 32; l++) s += sKh[l * 64 + tid];
        g_ks[(size_t)sub * DK + kh + tid] = s;
    }
}

// ---------------------------------------------------------------------------
// Kernel 2: exclusive prefix over 128 sub-chunks per batch, coalesced serial
// ---------------------------------------------------------------------------
__global__ void __launch_bounds__(512, 2)
k_scan(void) {
    if (blockIdx.x < 16) {
        const int t   = blockIdx.x * 512 + threadIdx.x;  // 0..8191
        const int row = t >> 5;                          // (b,v): 0..255
        const int k4  = (t & 31) * 4;
        const int b = row >> 7, v = row & 127;
        const size_t cstr = (size_t)DK * DV;
        const size_t base = (size_t)(b * NS) * cstr + (size_t)v * DK + k4;

        float4 run = make_float4(0.f, 0.f, 0.f, 0.f);
#pragma unroll 1
        for (int s = 0; s < NS; s += 4) {
            float4 x0 = *(const float4*)(g_kv + base + (size_t)(s + 0) * cstr);
            float4 x1 = *(const float4*)(g_kv + base + (size_t)(s + 1) * cstr);
            float4 x2 = *(const float4*)(g_kv + base + (size_t)(s + 2) * cstr);
            float4 x3 = *(const float4*)(g_kv + base + (size_t)(s + 3) * cstr);
            *(float4*)(g_kvpre + base + (size_t)(s + 0) * cstr) = run;
            run.x += x0.x; run.y += x0.y; run.z += x0.z; run.w += x0.w;
            *(float4*)(g_kvpre + base + (size_t)(s + 1) * cstr) = run;
            run.x += x1.x; run.y += x1.y; run.z += x1.z; run.w += x1.w;
            *(float4*)(g_kvpre + base + (size_t)(s + 2) * cstr) = run;
            run.x += x2.x; run.y += x2.y; run.z += x2.z; run.w += x2.w;
            *(float4*)(g_kvpre + base + (size_t)(s + 3) * cstr) = run;
            run.x += x3.x; run.y += x3.y; run.z += x3.z; run.w += x3.w;
        }
    } else if (threadIdx.x < 64) {
        const int b  = threadIdx.x >> 5;
        const int k4 = (threadIdx.x & 31) * 4;
        const size_t base = (size_t)(b * NS) * DK + k4;
        float4 run = make_float4(0.f, 0.f, 0.f, 0.f);
#pragma unroll 4
        for (int s = 0; s < NS; s++) {
            float4 x = *(const float4*)(g_ks + base + (size_t)s * DK);
            *(float4*)(g_kspre + base + (size_t)s * DK) = run;
            run.x += x.x; run.y += x.y; run.z += x.z; run.w += x.w;
        }
    }
}

// ---------------------------------------------------------------------------
// Kernel 3: per (chunk, v-half): A = mask(phiQ phiK^T); out = (A V + phiQ S)/Z
// grid = 256, 512 thr, ~101 KB smem (sK region reused for sVt+sSt), 2 CTA/SM.
// ---------------------------------------------------------------------------
constexpr int SM_Q  = 0;                       // [64][PK]
constexpr int SM_U  = SM_Q + C * PK;           // union: sK [64][PK]  OR  sVt[64][PL] + sSt[64][PK]
constexpr int SM_USZ = C * PL + C * PK;        // union size (12544 > C*PK=8320)
constexpr int SM_A  = SM_U + SM_USZ;           // [64][PJ]
constexpr int SM_KS = SM_A + C * PJ;           // [128]
constexpr int SM_Z  = SM_KS + DK;              // [64]
constexpr int SM_TOT = SM_Z + C;

__global__ void __launch_bounds__(512, 2)
k_output(const float* __restrict__ Q, const float* __restrict__ K,
         const float* __restrict__ V, float* __restrict__ out) {
    extern __shared__ float sm[];
    float* sQ  = sm + SM_Q;
    float* sK  = sm + SM_U;            // phase-1 life
    float* sVt = sm + SM_U;            // phase-2 life  [v-half 64][PL]
    float* sSt = sm + SM_U + C * PL;   // phase-2 life  [v-half 64][PK]
    float* sA  = sm + SM_A;
    float* sKs = sm + SM_KS;
    float* sZ  = sm + SM_Z;

    const int id = blockIdx.x;
    const int bc = id >> 1;
    const int vh = (id & 1) * 64;
    const int b  = bc / NC;
    const int c  = bc % NC;
    const int l0 = c * C;
    const int sub = bc * 2;            // prefix state before this chunk
    const int tid = threadIdx.x;

    // stage phiQ, phiK row-major: lane->k strided by 32, conflict-free STS
    for (int e = tid; e < 2048; e += 512) {
        const int l = e >> 5, kb = e & 31;
        const size_t g = ((size_t)(b * Lc + l0 + l)) * DK + kb;
        float* dq = &sQ[l * PK + kb];
        float* dk = &sK[l * PK + kb];
#pragma unroll
        for (int j = 0; j < 4; j++) {
            dq[j * 32] = phi(Q[g + j * 32]);
            dk[j * 32] = phi(K[g + j * 32]);
        }
    }
    if (tid < DK) sKs[tid] = g_kspre[(size_t)sub * DK + tid];
    if (tid < C)  sZ[tid] = 0.f;
    __syncthreads();

    const int w = tid >> 5, tx = tid & 31;
    const int half = tx >> 4, txl = tx & 15;

    // ---- phase 1: A[i][j] (pair over k). thread: 2 i x 4 j (j = txl + 16s) ----
    {
        const int i0 = w * 4 + half * 2;
        u64 aA[2][4] = {{0ull,0ull,0ull,0ull},{0ull,0ull,0ull,0ull}};
#pragma unroll 8
        for (int kp = 0; kp < DK / 2; kp++) {
            u64 a0 = lds64(&sQ[(i0    ) * PK + 2 * kp]);
            u64 a1 = lds64(&sQ[(i0 + 1) * PK + 2 * kp]);
            u64 bb[4];
#pragma unroll
            for (int s = 0; s < 4; s++) bb[s] = lds64(&sK[(txl + 16 * s) * PK + 2 * kp]);
#pragma unroll
            for (int s = 0; s < 4; s++) { fma2(aA[0][s], a0, bb[s]); fma2(aA[1][s], a1, bb[s]); }
        }
#pragma unroll
        for (int r = 0; r < 2; r++)
#pragma unroll
            for (int s = 0; s < 4; s++) {
                const int i = i0 + r, j = txl + 16 * s;
                float2 v = up2(aA[r][s]);
                sA[i * PJ + j] = (i >= j) ? (v.x + v.y) : 0.f;
            }
    }
    __syncthreads();   // sK reads complete; sA complete

    // ---- restage union region: Vt (v-half, transposed) + Spre [v][k] ----
    for (int e = tid; e < 1024; e += 512) {
        const int l = e >> 4, v4 = (e & 15) * 4;
        float4 x = *(const float4*)&V[((size_t)(b * Lc + l0 + l)) * DV + vh + v4];
        sVt[(v4 + 0) * PL + l] = x.x;
        sVt[(v4 + 1) * PL + l] = x.y;
        sVt[(v4 + 2) * PL + l] = x.z;
        sVt[(v4 + 3) * PL + l] = x.w;
    }
    {
        const float* Sp = g_kvpre + (size_t)sub * DK * DV;
        for (int e = tid; e < 2048; e += 512) {
            const int v = e >> 5, k4 = (e & 31) * 4;   // v local to half
            float4 x = *(const float4*)&Sp[(size_t)(vh + v) * DK + k4];
            *(float2*)&sSt[v * PK + k4]     = make_float2(x.x, x.y);
            *(float2*)&sSt[v * PK + k4 + 2] = make_float2(x.z, x.w);
        }
    }
    // ---- Z: rowsum(A) + phiQ . Kspre (8 partials per row) ----
    {
        const int iz = tid & 63, p = tid >> 6;
        float zp = 0.f;
#pragma unroll
        for (int j = p * 8; j < p * 8 + 8; j++) zp += sA[iz * PJ + j];
#pragma unroll
        for (int k = p * 16; k < p * 16 + 16; k++) zp += sQ[iz * PK + k] * sKs[k];
        atomicAdd(&sZ[iz], zp);
    }
    __syncthreads();

    // ---- phase 2: out = A V + phiQ Spre. thread: 4 i x 4 v (v = txl+16s) ----
    const int i0 = w * 4;                // warp-uniform rows
    u64 acc[4][4];
#pragma unroll
    for (int r = 0; r < 4; r++)
#pragma unroll
        for (int s = 0; s < 4; s++) acc[r][s] = 0ull;

#pragma unroll 4
    for (int jp = 0; jp < C / 2; jp++) {          // intra-chunk, pair over j
        u64 a[4], bb[4];
#pragma unroll
        for (int r = 0; r < 4; r++) a[r] = lds64(&sA[(i0 + r) * PJ + 2 * jp]);
#pragma unroll
        for (int s = 0; s < 4; s++) bb[s] = lds64(&sVt[(txl + 16 * s) * PL + 2 * jp]);
#pragma unroll
        for (int r = 0; r < 4; r++)
#pragma unroll
            for (int s = 0; s < 4; s++) fma2(acc[r][s], a[r], bb[s]);
    }
#pragma unroll 4
    for (int kp = 0; kp < DK / 2; kp++) {         // inter-chunk, pair over k
        u64 a[4], bb[4];
#pragma unroll
        for (int r = 0; r < 4; r++) a[r] = lds64(&sQ[(i0 + r) * PK + 2 * kp]);
#pragma unroll
        for (int s = 0; s < 4; s++) bb[s] = lds64(&sSt[(txl + 16 * s) * PK + 2 * kp]);
#pragma unroll
        for (int r = 0; r < 4; r++)
#pragma unroll
            for (int s = 0; s < 4; s++) fma2(acc[r][s], a[r], bb[s]);
    }

    // epilogue
#pragma unroll
    for (int r = 0; r < 4; r++) {
        const int i = i0 + r;
        const float invz = 1.f / (sZ[i] + EPS);
        const size_t g = ((size_t)(b * Lc + l0 + i)) * DV + vh;
#pragma unroll
        for (int s = 0; s < 4; s++) {
            float2 v = up2(acc[r][s]);
            out[g + txl + 16 * s] = (v.x + v.y) * invz;
        }
    }
}

// ---------------------------------------------------------------------------
extern "C" void kernel_launch(void* const* d_in, const int* in_sizes, int n_in,
                              void* d_out, int out_size) {
    const float* Q = (const float*)d_in[0];
    const float* K = (const float*)d_in[1];
    const float* V = (const float*)d_in[2];
    float* out = (float*)d_out;

    const int smem3 = SM_TOT * (int)sizeof(float);   // ~101 KB
    cudaFuncSetAttribute(k_output, cudaFuncAttributeMaxDynamicSharedMemorySize, smem3);

    k_chunk_kv<<<4 * TC, 256>>>(K, V);
    k_scan<<<17, 512>>>();
    k_output<<<2 * TC, 512, smem3>>>(Q, K, V, out);
}

// round 10
// speedup vs baseline: 1.7215x; 1.7215x over previous
#include <cuda_runtime.h>
#include <cuda_bf16.h>
#include <cstdint>

typedef unsigned long long u64;

constexpr int Bc = 2;
constexpr int Lc = 4096;
constexpr int DK = 128;
constexpr int DV = 128;
constexpr int C  = 64;
constexpr int NC = Lc / C;       // 64
constexpr int TC = Bc * NC;      // 128
constexpr float EPS = 1e-6f;

constexpr int PL = 66;           // l-contig stride (Vt in k3)
constexpr int PK = 130;          // k-contig stride (Q, K, Spre in k3)
constexpr int PJ = 66;           // j-contig stride (A in k3)

// Scratch: g_kv / g_kvpre stored [bc][v][k] (k contiguous)
__device__ float g_kv   [(size_t)TC * DK * DV];
__device__ float g_kvpre[(size_t)TC * DK * DV];
__device__ float g_ks   [(size_t)TC * DK];
__device__ float g_kspre[(size_t)TC * DK];

__device__ __forceinline__ float phi(float x) {
    return x > 0.f ? x + 1.f : __expf(x);
}
__device__ __forceinline__ void fma2(u64& d, u64 a, u64 b) {
    asm("fma.rn.f32x2 %0, %1, %2, %0;" : "+l"(d) : "l"(a), "l"(b));
}
__device__ __forceinline__ float2 up2(u64 v) {
    float2 f; asm("mov.b64 {%0, %1}, %2;" : "=f"(f.x), "=f"(f.y) : "l"(v)); return f;
}
__device__ __forceinline__ u64 lds64(const float* p) {
    return *reinterpret_cast<const u64*>(p);
}

// ---------------------------------------------------------------------------
// Kernel 1: KV[v][k] = sum_l phiK[l][k] V[l][v]  -> g_kv[bc][v][k]
// grid = 2*TC (chunk x v-half), 512 threads, 48 KB static smem.
// Pure scalar FFMA, 4k x 4v tile/thread: 2 LDS.128 + 16 FFMA per l.
// a-loads warp-broadcast (2 addrs), b-loads 2 clean wavefronts. No transposes.
// ---------------------------------------------------------------------------
__global__ void __launch_bounds__(512, 2)
k_chunk_kv(const float* __restrict__ K, const float* __restrict__ V) {
    __shared__ float sK[C * DK];    // 32 KB: phiK row-major (k contig)
    __shared__ float sV[C * 64];    // 16 KB: V half, row-major (v contig)

    const int bc = blockIdx.x >> 1;
    const int vh = (blockIdx.x & 1) * 64;
    const int b  = bc / NC;
    const int c  = bc % NC;
    const int l0 = c * C;
    const int tid = threadIdx.x;

    // stage phiK: coalesced LDG.128 -> conflict-free STS.128
    for (int e = tid; e < 2048; e += 512) {
        const int l = e >> 5, k4 = (e & 31) * 4;
        float4 x = *(const float4*)&K[((size_t)(b * Lc + l0 + l)) * DK + k4];
        *(float4*)&sK[l * DK + k4] = make_float4(phi(x.x), phi(x.y), phi(x.z), phi(x.w));
    }
    // stage V half: coalesced LDG.128 -> conflict-free STS.128
    for (int e = tid; e < 1024; e += 512) {
        const int l = e >> 4, v4 = (e & 15) * 4;
        float4 x = *(const float4*)&V[((size_t)(b * Lc + l0 + l)) * DV + vh + v4];
        *(float4*)&sV[l * 64 + v4] = x;
    }
    __syncthreads();

    const int k0 = (tid >> 4) * 4;   // 32 k-groups (warp: 2 broadcast addrs)
    const int v0 = (tid & 15) * 4;   // 16 v-groups

    float acc[4][4];
#pragma unroll
    for (int r = 0; r < 4; r++)
#pragma unroll
        for (int s = 0; s < 4; s++) acc[r][s] = 0.f;

#pragma unroll 4
    for (int l = 0; l < C; l++) {
        const float4 a = *(const float4*)&sK[l * DK + k0];
        const float4 bv = *(const float4*)&sV[l * 64 + v0];
        const float af[4] = {a.x, a.y, a.z, a.w};
        const float bf[4] = {bv.x, bv.y, bv.z, bv.w};
#pragma unroll
        for (int r = 0; r < 4; r++)
#pragma unroll
            for (int s = 0; s < 4; s++)
                acc[r][s] = fmaf(af[r], bf[s], acc[r][s]);
    }

    // store g_kv[bc][v][k]: per v one float4 over the 4 k's (k0 % 4 == 0)
    float* kvout = g_kv + (size_t)bc * DK * DV;
#pragma unroll
    for (int s = 0; s < 4; s++) {
        *(float4*)&kvout[(size_t)(vh + v0 + s) * DK + k0] =
            make_float4(acc[0][s], acc[1][s], acc[2][s], acc[3][s]);
    }

    // per-chunk phiK column sums (v-half 0 only): stride-128 reads, conflict-free
    if (vh == 0 && tid < DK) {
        float s = 0.f;
#pragma unroll 8
        for (int l = 0; l < C; l++) s += sK[l * DK + tid];
        g_ks[(size_t)bc * DK + tid] = s;
    }
}

// ---------------------------------------------------------------------------
// Kernel 2: warp-parallel exclusive scan over chunks (R5-proven)
// ---------------------------------------------------------------------------
__device__ __forceinline__ float warp_excl_scan(float x, int lane) {
#pragma unroll
    for (int d = 1; d < 32; d <<= 1) {
        float t = __shfl_up_sync(0xffffffffu, x, d);
        if (lane >= d) x += t;
    }
    float e = __shfl_up_sync(0xffffffffu, x, 1);
    return lane == 0 ? 0.f : e;
}

__global__ void __launch_bounds__(512, 2)
k_scan(void) {
    const int gw = blockIdx.x * 16 + (threadIdx.x >> 5);
    const int lane = threadIdx.x & 31;
    if (gw < 8192) {
        const int b   = gw >> 12;
        const int rem = gw & 4095;
        const int v   = rem >> 5;
        const int k4  = (rem & 31) * 4;
        const size_t cstr = (size_t)DK * DV;
        const size_t base = (size_t)(b * NC) * cstr + (size_t)v * DK + k4;

        float4 carry = make_float4(0.f, 0.f, 0.f, 0.f);
#pragma unroll
        for (int pass = 0; pass < 2; pass++) {
            const size_t idx = base + (size_t)(pass * 32 + lane) * cstr;
            float4 x = *(const float4*)(g_kv + idx);
            float4 ex;
            ex.x = warp_excl_scan(x.x, lane) + carry.x;
            ex.y = warp_excl_scan(x.y, lane) + carry.y;
            ex.z = warp_excl_scan(x.z, lane) + carry.z;
            ex.w = warp_excl_scan(x.w, lane) + carry.w;
            *(float4*)(g_kvpre + idx) = ex;
            carry.x = __shfl_sync(0xffffffffu, ex.x + x.x, 31);
            carry.y = __shfl_sync(0xffffffffu, ex.y + x.y, 31);
            carry.z = __shfl_sync(0xffffffffu, ex.z + x.z, 31);
            carry.w = __shfl_sync(0xffffffffu, ex.w + x.w, 31);
        }
    } else if (gw < 8192 + 64) {
        const int t  = gw - 8192;
        const int b  = t >> 5;
        const int k4 = (t & 31) * 4;
        const size_t base = (size_t)(b * NC) * DK + k4;
        float4 carry = make_float4(0.f, 0.f, 0.f, 0.f);
#pragma unroll
        for (int pass = 0; pass < 2; pass++) {
            const size_t idx = base + (size_t)(pass * 32 + lane) * DK;
            float4 x = *(const float4*)(g_ks + idx);
            float4 ex;
            ex.x = warp_excl_scan(x.x, lane) + carry.x;
            ex.y = warp_excl_scan(x.y, lane) + carry.y;
            ex.z = warp_excl_scan(x.z, lane) + carry.z;
            ex.w = warp_excl_scan(x.w, lane) + carry.w;
            *(float4*)(g_kspre + idx) = ex;
            carry.x = __shfl_sync(0xffffffffu, ex.x + x.x, 31);
            carry.y = __shfl_sync(0xffffffffu, ex.y + x.y, 31);
            carry.z = __shfl_sync(0xffffffffu, ex.z + x.z, 31);
            carry.w = __shfl_sync(0xffffffffu, ex.w + x.w, 31);
        }
    }
}

// ---------------------------------------------------------------------------
// Kernel 3: A = mask(phiQ phiK^T); out = (A V + phiQ Spre) / Z   (R5-proven)
// ---------------------------------------------------------------------------
__global__ void __launch_bounds__(512, 1)
k_output(const float* __restrict__ Q, const float* __restrict__ K,
         const float* __restrict__ V, float* __restrict__ out) {
    extern __shared__ float sm[];
    float* sQ  = sm;                        // [64][PK]
    float* sK  = sQ  + C * PK;              // [64][PK]
    float* sA  = sK  + C * PK;              // [64][PJ]
    float* sVt = sA  + C * PJ;              // [128][PL]
    float* sSt = sVt + DV * PL;             // [128][PK]
    float* sKs = sSt + DV * PK;             // [128]
    float* sZ  = sKs + DK;                  // [64]

    const int bc = blockIdx.x;
    const int b  = bc / NC;
    const int c  = bc % NC;
    const int l0 = c * C;
    const int tid = threadIdx.x;

    for (int e = tid; e < 2048; e += 512) {
        const int l = e >> 5, kb = e & 31;
        const size_t g = ((size_t)(b * Lc + l0 + l)) * DK + kb;
        float* dq = &sQ[l * PK + kb];
        float* dk = &sK[l * PK + kb];
#pragma unroll
        for (int j = 0; j < 4; j++) {
            dq[j * 32] = phi(Q[g + j * 32]);
            dk[j * 32] = phi(K[g + j * 32]);
        }
    }
    for (int e = tid; e < 2048; e += 512) {
        const int l = e >> 5, vb = e & 31;
        const float* src = &V[((size_t)(b * Lc + l0 + l)) * DV + vb];
        float* dst = &sVt[vb * PL + l];
#pragma unroll
        for (int j = 0; j < 4; j++)
            dst[j * 32 * PL] = src[j * 32];
    }
    {
        const float* Sp = g_kvpre + (size_t)bc * DK * DV;
        for (int e = tid; e < 4096; e += 512) {
            const int v = e >> 5, kb = e & 31;
            const float* src = &Sp[(size_t)v * DK + kb];
            float* dst = &sSt[v * PK + kb];
#pragma unroll
            for (int j = 0; j < 4; j++)
                dst[j * 32] = src[j * 32];
        }
    }
    if (tid < DK) sKs[tid] = g_kspre[(size_t)bc * DK + tid];
    if (tid < C)  sZ[tid] = 0.f;
    __syncthreads();

    const int w = tid >> 5, tx = tid & 31;
    const int half = tx >> 4, txl = tx & 15;

    {
        const int i0 = w * 4 + half * 2;
        u64 aA[2][4] = {{0ull,0ull,0ull,0ull},{0ull,0ull,0ull,0ull}};
#pragma unroll
        for (int kp = 0; kp < DK / 2; kp++) {
            u64 a0 = lds64(&sQ[(i0    ) * PK + 2 * kp]);
            u64 a1 = lds64(&sQ[(i0 + 1) * PK + 2 * kp]);
            u64 bb[4];
#pragma unroll
            for (int s = 0; s < 4; s++) bb[s] = lds64(&sK[(txl + 16 * s) * PK + 2 * kp]);
#pragma unroll
            for (int s = 0; s < 4; s++) { fma2(aA[0][s], a0, bb[s]); fma2(aA[1][s], a1, bb[s]); }
        }
#pragma unroll
        for (int r = 0; r < 2; r++)
#pragma unroll
            for (int s = 0; s < 4; s++) {
                const int i = i0 + r, j = txl + 16 * s;
                float2 v = up2(aA[r][s]);
                sA[i * PJ + j] = (i >= j) ? (v.x + v.y) : 0.f;
            }
    }
    __syncthreads();

    {
        const int iz = tid & 63, p = tid >> 6;
        float zp = 0.f;
#pragma unroll
        for (int j = p * 8; j < p * 8 + 8; j++) zp += sA[iz * PJ + j];
#pragma unroll
        for (int k = p * 16; k < p * 16 + 16; k++) zp += sQ[iz * PK + k] * sKs[k];
        atomicAdd(&sZ[iz], zp);
    }

    const int i0 = (w & 7) * 8 + half * 4;
    const int vg = (w >> 3) * 64;
    u64 acc[4][4];
#pragma unroll
    for (int r = 0; r < 4; r++)
#pragma unroll
        for (int s = 0; s < 4; s++) acc[r][s] = 0ull;

#pragma unroll
    for (int jp = 0; jp < C / 2; jp++) {
        u64 a[4], bb[4];
#pragma unroll
        for (int r = 0; r < 4; r++) a[r] = lds64(&sA[(i0 + r) * PJ + 2 * jp]);
#pragma unroll
        for (int s = 0; s < 4; s++) bb[s] = lds64(&sVt[(vg + txl + 16 * s) * PL + 2 * jp]);
#pragma unroll
        for (int r = 0; r < 4; r++)
#pragma unroll
            for (int s = 0; s < 4; s++) fma2(acc[r][s], a[r], bb[s]);
    }
#pragma unroll
    for (int kp = 0; kp < DK / 2; kp++) {
        u64 a[4], bb[4];
#pragma unroll
        for (int r = 0; r < 4; r++) a[r] = lds64(&sQ[(i0 + r) * PK + 2 * kp]);
#pragma unroll
        for (int s = 0; s < 4; s++) bb[s] = lds64(&sSt[(vg + txl + 16 * s) * PK + 2 * kp]);
#pragma unroll
        for (int r = 0; r < 4; r++)
#pragma unroll
            for (int s = 0; s < 4; s++) fma2(acc[r][s], a[r], bb[s]);
    }

    __syncthreads();

#pragma unroll
    for (int r = 0; r < 4; r++) {
        const int i = i0 + r;
        const float invz = 1.f / (sZ[i] + EPS);
        const size_t g = ((size_t)(b * Lc + l0 + i)) * DV;
#pragma unroll
        for (int s = 0; s < 4; s++) {
            float2 v = up2(acc[r][s]);
            out[g + vg + txl + 16 * s] = (v.x + v.y) * invz;
        }
    }
}

// ---------------------------------------------------------------------------
extern "C" void kernel_launch(void* const* d_in, const int* in_sizes, int n_in,
                              void* d_out, int out_size) {
    const float* Q = (const float*)d_in[0];
    const float* K = (const float*)d_in[1];
    const float* V = (const float*)d_in[2];
    float* out = (float*)d_out;

    const int smem3 = (2 * C * PK + C * PJ + DV * PL + DV * PK + DK + C)
                      * (int)sizeof(float);                                      // ~184.6 KB

    cudaFuncSetAttribute(k_output, cudaFuncAttributeMaxDynamicSharedMemorySize, smem3);

    k_chunk_kv<<<2 * TC, 512>>>(K, V);
    k_scan<<<516, 512>>>();
    k_output<<<TC, 512, smem3>>>(Q, K, V, out);
}